// round 1
// baseline (speedup 1.0000x reference)
#include <cuda_runtime.h>

#define BB 128
#define SS 512
#define EE 512
#define HH 1024
#define VV 32000
#define NC 1000

// Scratch (static device allocations are allowed)
__device__ float g_pt[(size_t)VV * 2048];     // [vocab][2048]: cols 0..1023 = z-preact(+bz), 1024..2047 = h-preact(+bh)
__device__ float g_wt3[128 * 1024 * 16];      // per-block recurrent weight image: [nb][k][g*8+c]
__device__ float g_wfc3[125 * 1024 * 8];      // per-block classifier weight image: [nb][k][c]
__device__ float g_h[2][BB * HH];             // double-buffered hidden state

// ---- packed f32x2 helpers (FFMA2: 2 MACs/lane, full fp32 rate on sm_103a) ----
__device__ __forceinline__ unsigned long long pack2(float a, float b) {
    unsigned long long r;
    asm("mov.b64 %0, {%1, %2};" : "=l"(r) : "f"(a), "f"(b));
    return r;
}
__device__ __forceinline__ void unpack2(unsigned long long v, float& a, float& b) {
    asm("mov.b64 {%0, %1}, %2;" : "=f"(a), "=f"(b) : "l"(v));
}
__device__ __forceinline__ void ffma2(unsigned long long& d, unsigned long long a, unsigned long long b) {
    asm("fma.rn.f32x2 %0, %1, %2, %0;" : "+l"(d) : "l"(a), "l"(b));
}

// ---------------------------------------------------------------------------
// Prep: swizzle recurrent weights into per-block SMEM images.
// g_wt3[nb*16384 + k*16 + g*8 + c] = W_g[(512+k)*1024 + nb*8 + c]
// ---------------------------------------------------------------------------
__global__ void prep_wt(const float* __restrict__ Wz, const float* __restrict__ Wh) {
    int o = blockIdx.x * blockDim.x + threadIdx.x;
    if (o >= 128 * 1024 * 16) return;
    int c = o & 7, g = (o >> 3) & 1, k = (o >> 4) & 1023, nb = o >> 14;
    const float* W = g ? Wh : Wz;
    g_wt3[o] = W[(size_t)(512 + k) * 1024 + nb * 8 + c];
}

__global__ void prep_wfc(const float* __restrict__ Wfc) {
    int o = blockIdx.x * blockDim.x + threadIdx.x;
    if (o >= 125 * 1024 * 8) return;
    int c = o & 7, k = (o >> 3) & 1023, nb = o >> 13;
    g_wfc3[o] = Wfc[(size_t)k * NC + nb * 8 + c];
}

__global__ void zero_h0() {
    int i = blockIdx.x * blockDim.x + threadIdx.x;
    if (i < BB * HH) g_h[0][i] = 0.0f;
}

// ---------------------------------------------------------------------------
// ptable GEMM: P[32000 x 2048] = emb[32000 x 512] @ [Wz_top | Wh_top] + bias
// 128x128 block tile, BK=8, 256 threads, 8x8 micro-tile, FFMA2 inner loop.
// ---------------------------------------------------------------------------
__global__ __launch_bounds__(256) void ptable_gemm(
    const float* __restrict__ emb,
    const float* __restrict__ Wz, const float* __restrict__ Wh,
    const float* __restrict__ bz, const float* __restrict__ bh)
{
    __shared__ float As[8][132];
    __shared__ float Bs[8][128];
    const int tid = threadIdx.x;
    const int tx = tid & 15, ty = tid >> 4;
    const int row0 = blockIdx.y * 128;
    const int col0 = blockIdx.x * 128;
    const float* W = (col0 < 1024) ? Wz : Wh;
    const int ccol0 = col0 & 1023;

    unsigned long long acc[8][4];
#pragma unroll
    for (int i = 0; i < 8; i++)
#pragma unroll
        for (int j = 0; j < 4; j++) acc[i][j] = 0ull;

    const int arow = tid >> 1;
    const int akq = (tid & 1) * 4;
    const int bkk = tid >> 5;
    const int bj = (tid & 31) * 4;

    for (int k0 = 0; k0 < EE; k0 += 8) {
        float4 av = *(const float4*)(emb + (size_t)(row0 + arow) * EE + k0 + akq);
        float4 bv = *(const float4*)(W + (size_t)(k0 + bkk) * HH + ccol0 + bj);
        As[akq + 0][arow] = av.x;
        As[akq + 1][arow] = av.y;
        As[akq + 2][arow] = av.z;
        As[akq + 3][arow] = av.w;
        *(float4*)&Bs[bkk][bj] = bv;
        __syncthreads();
#pragma unroll
        for (int kk = 0; kk < 8; kk++) {
            float4 a0 = *(const float4*)&As[kk][ty * 8];
            float4 a1 = *(const float4*)&As[kk][ty * 8 + 4];
            ulonglong2 b0 = *(const ulonglong2*)&Bs[kk][tx * 8];
            ulonglong2 b1 = *(const ulonglong2*)&Bs[kk][tx * 8 + 4];
            float a[8] = {a0.x, a0.y, a0.z, a0.w, a1.x, a1.y, a1.z, a1.w};
#pragma unroll
            for (int i = 0; i < 8; i++) {
                unsigned long long hh = pack2(a[i], a[i]);
                ffma2(acc[i][0], hh, b0.x);
                ffma2(acc[i][1], hh, b0.y);
                ffma2(acc[i][2], hh, b1.x);
                ffma2(acc[i][3], hh, b1.y);
            }
        }
        __syncthreads();
    }

    const float* bias = (col0 < 1024) ? bz : bh;
    const int colg = ccol0 + tx * 8;
    float bvv[8];
#pragma unroll
    for (int j = 0; j < 8; j++) bvv[j] = bias[colg + j];
#pragma unroll
    for (int i = 0; i < 8; i++) {
        float v[8];
        unpack2(acc[i][0], v[0], v[1]);
        unpack2(acc[i][1], v[2], v[3]);
        unpack2(acc[i][2], v[4], v[5]);
        unpack2(acc[i][3], v[6], v[7]);
#pragma unroll
        for (int j = 0; j < 8; j++) v[j] += bvv[j];
        int row = row0 + ty * 8 + i;
        float* dst = g_pt + (size_t)row * 2048 + col0 + tx * 8;
        *(float4*)dst = make_float4(v[0], v[1], v[2], v[3]);
        *(float4*)(dst + 4) = make_float4(v[4], v[5], v[6], v[7]);
    }
}

// ---------------------------------------------------------------------------
// One recurrence step. Grid = 128 blocks x 512 threads.
// Block nb owns h-columns c0..c0+7 of BOTH gates -> local gate update.
// Thread = (r = tid&127, g = bit7, kh = bit8): kh splits K=1024 in half.
// ---------------------------------------------------------------------------
#define STEP_SMEM_FLOATS (16384 + 2 * 8320 + 2 * 2 * 1152)
__global__ __launch_bounds__(512) void step_kernel(const int* __restrict__ x, int t) {
    extern __shared__ float sm[];
    float* ws = sm;                        // 16384: weights [k][g*8+c]
    float* hsm = sm + 16384;               // 2 regions * 128*65
    float* part = sm + 16384 + 2 * 8320;   // partials [kh][g][r*9+c]
    const int tid = threadIdx.x;
    const int nb = blockIdx.x;
    const int c0 = nb * 8;
    const int p = t & 1;
    const float* __restrict__ hin = g_h[p];
    float* __restrict__ hout = g_h[p ^ 1];

    // coalesced linear copy of this block's pre-swizzled weight image
    {
        const float4* src = (const float4*)(g_wt3 + nb * 16384);
        float4* dst = (float4*)ws;
#pragma unroll
        for (int i = 0; i < 8; i++) dst[tid + i * 512] = src[tid + i * 512];
    }

    const int r = tid & 127;
    const int g = (tid >> 7) & 1;
    const int kh = tid >> 8;

    unsigned long long a0 = 0, a1 = 0, a2 = 0, a3 = 0;
    if (kh == 0) {
        int tok = x[r * SS + t];
        const float* pt = g_pt + (size_t)tok * 2048 + (g << 10) + c0;
        float4 p0 = *(const float4*)pt;
        float4 p1 = *(const float4*)(pt + 4);
        a0 = pack2(p0.x, p0.y); a1 = pack2(p0.z, p0.w);
        a2 = pack2(p1.x, p1.y); a3 = pack2(p1.z, p1.w);
    }

    for (int j = 0; j < 8; j++) {
        __syncthreads();
        // stage two 128x64 h-chunks (one per k-half)
#pragma unroll
        for (int i = 0; i < 8; i++) {
            int idx = tid + i * 512;          // 0..4095 float4 slots
            int region = idx >> 11;
            int rem = idx & 2047;
            int rr = rem >> 4;
            int kq = (rem & 15) << 2;
            float4 hv = *(const float4*)(hin + rr * HH + region * 512 + j * 64 + kq);
            float* d = hsm + region * 8320 + rr * 65 + kq;
            d[0] = hv.x; d[1] = hv.y; d[2] = hv.z; d[3] = hv.w;
        }
        __syncthreads();
        const float* hrow = hsm + kh * 8320 + r * 65;
        const ulonglong2* wp = (const ulonglong2*)(ws + (kh * 512 + j * 64) * 16 + g * 8);
#pragma unroll
        for (int k = 0; k < 64; k++) {
            float hv = hrow[k];
            unsigned long long hh = pack2(hv, hv);
            ulonglong2 w0 = wp[k * 4];
            ulonglong2 w1 = wp[k * 4 + 1];
            ffma2(a0, hh, w0.x);
            ffma2(a1, hh, w0.y);
            ffma2(a2, hh, w1.x);
            ffma2(a3, hh, w1.y);
        }
    }

    float v[8];
    unpack2(a0, v[0], v[1]); unpack2(a1, v[2], v[3]);
    unpack2(a2, v[4], v[5]); unpack2(a3, v[6], v[7]);
    float* pp = part + kh * 2304 + g * 1152 + r * 9;
#pragma unroll
    for (int c = 0; c < 8; c++) pp[c] = v[c];
    __syncthreads();
    if (kh == 0) {
        float* q = part + g * 1152 + r * 9;
#pragma unroll
        for (int c = 0; c < 8; c++) {
            float s = q[c] + q[2304 + c];
            q[c] = g ? tanhf(s) : 1.0f / (1.0f + __expf(-s));
        }
    }
    __syncthreads();
    if (tid < 128) {  // kh==0, g==0
#pragma unroll
        for (int c = 0; c < 8; c++) {
            float z = part[r * 9 + c];
            float ht = part[1152 + r * 9 + c];
            float hp = hin[r * HH + c0 + c];
            hout[r * HH + c0 + c] = (1.0f - z) * hp + z * ht;
        }
    }
}

// ---------------------------------------------------------------------------
// Final classifier: out[128 x 1000] = h_final @ Wfc + bfc. 125 blocks x 256.
// ---------------------------------------------------------------------------
#define FINAL_SMEM_FLOATS (8192 + 2 * 4224 + 1152)
__global__ __launch_bounds__(256) void final_kernel(const float* __restrict__ bfc,
                                                    float* __restrict__ out) {
    extern __shared__ float sm[];
    float* ws = sm;                   // 8192: Wfc slice [k][c]
    float* hsm = sm + 8192;           // 2 regions * 128*33
    float* red = sm + 8192 + 2 * 4224;
    const int tid = threadIdx.x;
    const int nb = blockIdx.x;
    const int c0 = nb * 8;
    const float* hin = g_h[0];
    {
        const float4* src = (const float4*)(g_wfc3 + nb * 8192);
        float4* dst = (float4*)ws;
#pragma unroll
        for (int i = 0; i < 8; i++) dst[tid + i * 256] = src[tid + i * 256];
    }
    const int r = tid & 127, kh = tid >> 7;
    unsigned long long a0 = 0, a1 = 0, a2 = 0, a3 = 0;

    for (int j = 0; j < 16; j++) {
        __syncthreads();
#pragma unroll
        for (int i = 0; i < 8; i++) {
            int idx = tid + i * 256;      // 0..2047 float4 slots
            int region = idx >> 10;
            int rem = idx & 1023;
            int rr = rem >> 3;
            int kq = (rem & 7) << 2;
            float4 hv = *(const float4*)(hin + rr * HH + region * 512 + j * 32 + kq);
            float* d = hsm + region * 4224 + rr * 33 + kq;
            d[0] = hv.x; d[1] = hv.y; d[2] = hv.z; d[3] = hv.w;
        }
        __syncthreads();
        const float* hrow = hsm + kh * 4224 + r * 33;
        const ulonglong2* wp = (const ulonglong2*)(ws + (kh * 512 + j * 32) * 8);
#pragma unroll
        for (int k = 0; k < 32; k++) {
            float hv = hrow[k];
            unsigned long long hh = pack2(hv, hv);
            ulonglong2 w0 = wp[k * 2];
            ulonglong2 w1 = wp[k * 2 + 1];
            ffma2(a0, hh, w0.x);
            ffma2(a1, hh, w0.y);
            ffma2(a2, hh, w1.x);
            ffma2(a3, hh, w1.y);
        }
    }
    float v[8];
    unpack2(a0, v[0], v[1]); unpack2(a1, v[2], v[3]);
    unpack2(a2, v[4], v[5]); unpack2(a3, v[6], v[7]);
    if (kh == 1) {
#pragma unroll
        for (int c = 0; c < 8; c++) red[r * 9 + c] = v[c];
    }
    __syncthreads();
    if (kh == 0) {
#pragma unroll
        for (int c = 0; c < 8; c++)
            out[r * NC + c0 + c] = v[c] + red[r * 9 + c] + bfc[c0 + c];
    }
}

// ---------------------------------------------------------------------------
extern "C" void kernel_launch(void* const* d_in, const int* in_sizes, int n_in,
                              void* d_out, int out_size) {
    const int*   x   = (const int*)  d_in[0];
    const float* emb = (const float*)d_in[1];
    const float* Wz  = (const float*)d_in[2];
    const float* bz  = (const float*)d_in[3];
    const float* Wh  = (const float*)d_in[4];
    const float* bh  = (const float*)d_in[5];
    const float* Wfc = (const float*)d_in[6];
    const float* bfc = (const float*)d_in[7];
    float* out = (float*)d_out;
    (void)in_sizes; (void)n_in; (void)out_size;

    const int step_smem = STEP_SMEM_FLOATS * 4;
    const int final_smem = FINAL_SMEM_FLOATS * 4;
    cudaFuncSetAttribute(step_kernel, cudaFuncAttributeMaxDynamicSharedMemorySize, step_smem);
    cudaFuncSetAttribute(final_kernel, cudaFuncAttributeMaxDynamicSharedMemorySize, final_smem);

    prep_wt<<<(128 * 1024 * 16) / 256, 256>>>(Wz, Wh);
    prep_wfc<<<(125 * 1024 * 8 + 255) / 256, 256>>>(Wfc);
    zero_h0<<<(BB * HH) / 256, 256>>>();
    ptable_gemm<<<dim3(16, 250), 256>>>(emb, Wz, Wh, bz, bh);

    for (int t = 0; t < SS; t++)
        step_kernel<<<128, 512, step_smem>>>(x, t);

    final_kernel<<<125, 256, final_smem>>>(bfc, out);
}

// round 2
// speedup vs baseline: 1.0002x; 1.0002x over previous
#include <cuda_runtime.h>

#define BB 128
#define SS 512
#define EE 512
#define HH 1024
#define VV 32000
#define NC 1000

// Scratch (static device allocations are allowed)
__device__ float g_pt[(size_t)VV * 2048];     // [vocab][2048]: cols 0..1023 = z-preact(+bz), 1024..2047 = h-preact(+bh)
__device__ float g_wt3[128 * 1024 * 16];      // per-block recurrent weight image: [nb][k][g*8+c]
__device__ float g_wfc3[125 * 1024 * 8];      // per-block classifier weight image: [nb][k][c]
__device__ float g_h[2][BB * HH];             // double-buffered hidden state

// ---- packed f32x2 helpers (FFMA2: 2 MACs/lane, full fp32 rate on sm_103a) ----
__device__ __forceinline__ unsigned long long pack2(float a, float b) {
    unsigned long long r;
    asm("mov.b64 %0, {%1, %2};" : "=l"(r) : "f"(a), "f"(b));
    return r;
}
__device__ __forceinline__ void unpack2(unsigned long long v, float& a, float& b) {
    asm("mov.b64 {%0, %1}, %2;" : "=f"(a), "=f"(b) : "l"(v));
}
__device__ __forceinline__ void ffma2(unsigned long long& d, unsigned long long a, unsigned long long b) {
    asm("fma.rn.f32x2 %0, %1, %2, %0;" : "+l"(d) : "l"(a), "l"(b));
}

// ---------------------------------------------------------------------------
// Prep: swizzle recurrent weights into per-block SMEM images.
// g_wt3[nb*16384 + k*16 + g*8 + c] = W_g[(512+k)*1024 + nb*8 + c]
// ---------------------------------------------------------------------------
__global__ void prep_wt(const float* __restrict__ Wz, const float* __restrict__ Wh) {
    int o = blockIdx.x * blockDim.x + threadIdx.x;
    if (o >= 128 * 1024 * 16) return;
    int c = o & 7, g = (o >> 3) & 1, k = (o >> 4) & 1023, nb = o >> 14;
    const float* W = g ? Wh : Wz;
    g_wt3[o] = W[(size_t)(512 + k) * 1024 + nb * 8 + c];
}

__global__ void prep_wfc(const float* __restrict__ Wfc) {
    int o = blockIdx.x * blockDim.x + threadIdx.x;
    if (o >= 125 * 1024 * 8) return;
    int c = o & 7, k = (o >> 3) & 1023, nb = o >> 13;
    g_wfc3[o] = Wfc[(size_t)k * NC + nb * 8 + c];
}

__global__ void zero_h0() {
    int i = blockIdx.x * blockDim.x + threadIdx.x;
    if (i < BB * HH) g_h[0][i] = 0.0f;
}

// ---------------------------------------------------------------------------
// ptable GEMM: P[32000 x 2048] = emb[32000 x 512] @ [Wz_top | Wh_top] + bias
// 128x128 block tile, BK=8, 256 threads, 8x8 micro-tile, FFMA2 inner loop.
// ---------------------------------------------------------------------------
__global__ __launch_bounds__(256) void ptable_gemm(
    const float* __restrict__ emb,
    const float* __restrict__ Wz, const float* __restrict__ Wh,
    const float* __restrict__ bz, const float* __restrict__ bh)
{
    __shared__ float As[8][132];
    __shared__ float Bs[8][128];
    const int tid = threadIdx.x;
    const int tx = tid & 15, ty = tid >> 4;
    const int row0 = blockIdx.y * 128;
    const int col0 = blockIdx.x * 128;
    const float* W = (col0 < 1024) ? Wz : Wh;
    const int ccol0 = col0 & 1023;

    unsigned long long acc[8][4];
#pragma unroll
    for (int i = 0; i < 8; i++)
#pragma unroll
        for (int j = 0; j < 4; j++) acc[i][j] = 0ull;

    const int arow = tid >> 1;
    const int akq = (tid & 1) * 4;
    const int bkk = tid >> 5;
    const int bj = (tid & 31) * 4;

    for (int k0 = 0; k0 < EE; k0 += 8) {
        float4 av = *(const float4*)(emb + (size_t)(row0 + arow) * EE + k0 + akq);
        float4 bv = *(const float4*)(W + (size_t)(k0 + bkk) * HH + ccol0 + bj);
        As[akq + 0][arow] = av.x;
        As[akq + 1][arow] = av.y;
        As[akq + 2][arow] = av.z;
        As[akq + 3][arow] = av.w;
        *(float4*)&Bs[bkk][bj] = bv;
        __syncthreads();
#pragma unroll
        for (int kk = 0; kk < 8; kk++) {
            float4 a0 = *(const float4*)&As[kk][ty * 8];
            float4 a1 = *(const float4*)&As[kk][ty * 8 + 4];
            ulonglong2 b0 = *(const ulonglong2*)&Bs[kk][tx * 8];
            ulonglong2 b1 = *(const ulonglong2*)&Bs[kk][tx * 8 + 4];
            float a[8] = {a0.x, a0.y, a0.z, a0.w, a1.x, a1.y, a1.z, a1.w};
#pragma unroll
            for (int i = 0; i < 8; i++) {
                unsigned long long hh = pack2(a[i], a[i]);
                ffma2(acc[i][0], hh, b0.x);
                ffma2(acc[i][1], hh, b0.y);
                ffma2(acc[i][2], hh, b1.x);
                ffma2(acc[i][3], hh, b1.y);
            }
        }
        __syncthreads();
    }

    const float* bias = (col0 < 1024) ? bz : bh;
    const int colg = ccol0 + tx * 8;
    float bvv[8];
#pragma unroll
    for (int j = 0; j < 8; j++) bvv[j] = bias[colg + j];
#pragma unroll
    for (int i = 0; i < 8; i++) {
        float v[8];
        unpack2(acc[i][0], v[0], v[1]);
        unpack2(acc[i][1], v[2], v[3]);
        unpack2(acc[i][2], v[4], v[5]);
        unpack2(acc[i][3], v[6], v[7]);
#pragma unroll
        for (int j = 0; j < 8; j++) v[j] += bvv[j];
        int row = row0 + ty * 8 + i;
        float* dst = g_pt + (size_t)row * 2048 + col0 + tx * 8;
        *(float4*)dst = make_float4(v[0], v[1], v[2], v[3]);
        *(float4*)(dst + 4) = make_float4(v[4], v[5], v[6], v[7]);
    }
}

// ---------------------------------------------------------------------------
// One recurrence step. Grid = 128 blocks x 512 threads.
// Block nb owns h-columns c0..c0+7 of BOTH gates -> local gate update.
// Thread = (r = tid&127, g = bit7, kh = bit8): kh splits K=1024 in half.
// ---------------------------------------------------------------------------
#define STEP_SMEM_FLOATS (16384 + 2 * 8320 + 2 * 2 * 1152)
__global__ __launch_bounds__(512) void step_kernel(const int* __restrict__ x, int t) {
    extern __shared__ float sm[];
    float* ws = sm;                        // 16384: weights [k][g*8+c]
    float* hsm = sm + 16384;               // 2 regions * 128*65
    float* part = sm + 16384 + 2 * 8320;   // partials [kh][g][r*9+c]
    const int tid = threadIdx.x;
    const int nb = blockIdx.x;
    const int c0 = nb * 8;
    const int p = t & 1;
    const float* __restrict__ hin = g_h[p];
    float* __restrict__ hout = g_h[p ^ 1];

    // coalesced linear copy of this block's pre-swizzled weight image
    {
        const float4* src = (const float4*)(g_wt3 + nb * 16384);
        float4* dst = (float4*)ws;
#pragma unroll
        for (int i = 0; i < 8; i++) dst[tid + i * 512] = src[tid + i * 512];
    }

    const int r = tid & 127;
    const int g = (tid >> 7) & 1;
    const int kh = tid >> 8;

    unsigned long long a0 = 0, a1 = 0, a2 = 0, a3 = 0;
    if (kh == 0) {
        int tok = x[r * SS + t];
        const float* pt = g_pt + (size_t)tok * 2048 + (g << 10) + c0;
        float4 p0 = *(const float4*)pt;
        float4 p1 = *(const float4*)(pt + 4);
        a0 = pack2(p0.x, p0.y); a1 = pack2(p0.z, p0.w);
        a2 = pack2(p1.x, p1.y); a3 = pack2(p1.z, p1.w);
    }

    for (int j = 0; j < 8; j++) {
        __syncthreads();
        // stage two 128x64 h-chunks (one per k-half)
#pragma unroll
        for (int i = 0; i < 8; i++) {
            int idx = tid + i * 512;          // 0..4095 float4 slots
            int region = idx >> 11;
            int rem = idx & 2047;
            int rr = rem >> 4;
            int kq = (rem & 15) << 2;
            float4 hv = *(const float4*)(hin + rr * HH + region * 512 + j * 64 + kq);
            float* d = hsm + region * 8320 + rr * 65 + kq;
            d[0] = hv.x; d[1] = hv.y; d[2] = hv.z; d[3] = hv.w;
        }
        __syncthreads();
        const float* hrow = hsm + kh * 8320 + r * 65;
        const ulonglong2* wp = (const ulonglong2*)(ws + (kh * 512 + j * 64) * 16 + g * 8);
#pragma unroll
        for (int k = 0; k < 64; k++) {
            float hv = hrow[k];
            unsigned long long hh = pack2(hv, hv);
            ulonglong2 w0 = wp[k * 4];
            ulonglong2 w1 = wp[k * 4 + 1];
            ffma2(a0, hh, w0.x);
            ffma2(a1, hh, w0.y);
            ffma2(a2, hh, w1.x);
            ffma2(a3, hh, w1.y);
        }
    }

    float v[8];
    unpack2(a0, v[0], v[1]); unpack2(a1, v[2], v[3]);
    unpack2(a2, v[4], v[5]); unpack2(a3, v[6], v[7]);
    float* pp = part + kh * 2304 + g * 1152 + r * 9;
#pragma unroll
    for (int c = 0; c < 8; c++) pp[c] = v[c];
    __syncthreads();
    if (kh == 0) {
        float* q = part + g * 1152 + r * 9;
#pragma unroll
        for (int c = 0; c < 8; c++) {
            float s = q[c] + q[2304 + c];
            q[c] = g ? tanhf(s) : 1.0f / (1.0f + __expf(-s));
        }
    }
    __syncthreads();
    if (tid < 128) {  // kh==0, g==0
#pragma unroll
        for (int c = 0; c < 8; c++) {
            float z = part[r * 9 + c];
            float ht = part[1152 + r * 9 + c];
            float hp = hin[r * HH + c0 + c];
            hout[r * HH + c0 + c] = (1.0f - z) * hp + z * ht;
        }
    }
}

// ---------------------------------------------------------------------------
// Final classifier: out[128 x 1000] = h_final @ Wfc + bfc. 125 blocks x 256.
// ---------------------------------------------------------------------------
#define FINAL_SMEM_FLOATS (8192 + 2 * 4224 + 1152)
__global__ __launch_bounds__(256) void final_kernel(const float* __restrict__ bfc,
                                                    float* __restrict__ out) {
    extern __shared__ float sm[];
    float* ws = sm;                   // 8192: Wfc slice [k][c]
    float* hsm = sm + 8192;           // 2 regions * 128*33
    float* red = sm + 8192 + 2 * 4224;
    const int tid = threadIdx.x;
    const int nb = blockIdx.x;
    const int c0 = nb * 8;
    const float* hin = g_h[0];
    {
        const float4* src = (const float4*)(g_wfc3 + nb * 8192);
        float4* dst = (float4*)ws;
#pragma unroll
        for (int i = 0; i < 8; i++) dst[tid + i * 256] = src[tid + i * 256];
    }
    const int r = tid & 127, kh = tid >> 7;
    unsigned long long a0 = 0, a1 = 0, a2 = 0, a3 = 0;

    for (int j = 0; j < 16; j++) {
        __syncthreads();
#pragma unroll
        for (int i = 0; i < 8; i++) {
            int idx = tid + i * 256;      // 0..2047 float4 slots
            int region = idx >> 10;
            int rem = idx & 1023;
            int rr = rem >> 3;
            int kq = (rem & 7) << 2;
            float4 hv = *(const float4*)(hin + rr * HH + region * 512 + j * 32 + kq);
            float* d = hsm + region * 4224 + rr * 33 + kq;
            d[0] = hv.x; d[1] = hv.y; d[2] = hv.z; d[3] = hv.w;
        }
        __syncthreads();
        const float* hrow = hsm + kh * 4224 + r * 33;
        const ulonglong2* wp = (const ulonglong2*)(ws + (kh * 512 + j * 32) * 8);
#pragma unroll
        for (int k = 0; k < 32; k++) {
            float hv = hrow[k];
            unsigned long long hh = pack2(hv, hv);
            ulonglong2 w0 = wp[k * 2];
            ulonglong2 w1 = wp[k * 2 + 1];
            ffma2(a0, hh, w0.x);
            ffma2(a1, hh, w0.y);
            ffma2(a2, hh, w1.x);
            ffma2(a3, hh, w1.y);
        }
    }
    float v[8];
    unpack2(a0, v[0], v[1]); unpack2(a1, v[2], v[3]);
    unpack2(a2, v[4], v[5]); unpack2(a3, v[6], v[7]);
    if (kh == 1) {
#pragma unroll
        for (int c = 0; c < 8; c++) red[r * 9 + c] = v[c];
    }
    __syncthreads();
    if (kh == 0) {
#pragma unroll
        for (int c = 0; c < 8; c++)
            out[r * NC + c0 + c] = v[c] + red[r * 9 + c] + bfc[c0 + c];
    }
}

// ---------------------------------------------------------------------------
extern "C" void kernel_launch(void* const* d_in, const int* in_sizes, int n_in,
                              void* d_out, int out_size) {
    const int*   x   = (const int*)  d_in[0];
    const float* emb = (const float*)d_in[1];
    const float* Wz  = (const float*)d_in[2];
    const float* bz  = (const float*)d_in[3];
    const float* Wh  = (const float*)d_in[4];
    const float* bh  = (const float*)d_in[5];
    const float* Wfc = (const float*)d_in[6];
    const float* bfc = (const float*)d_in[7];
    float* out = (float*)d_out;
    (void)in_sizes; (void)n_in; (void)out_size;

    const int step_smem = STEP_SMEM_FLOATS * 4;
    const int final_smem = FINAL_SMEM_FLOATS * 4;
    cudaFuncSetAttribute(step_kernel, cudaFuncAttributeMaxDynamicSharedMemorySize, step_smem);
    cudaFuncSetAttribute(final_kernel, cudaFuncAttributeMaxDynamicSharedMemorySize, final_smem);

    prep_wt<<<(128 * 1024 * 16) / 256, 256>>>(Wz, Wh);
    prep_wfc<<<(125 * 1024 * 8 + 255) / 256, 256>>>(Wfc);
    zero_h0<<<(BB * HH) / 256, 256>>>();
    ptable_gemm<<<dim3(16, 250), 256>>>(emb, Wz, Wh, bz, bh);

    for (int t = 0; t < SS; t++)
        step_kernel<<<128, 512, step_smem>>>(x, t);

    final_kernel<<<125, 256, final_smem>>>(bfc, out);
}

// round 3
// speedup vs baseline: 1.4349x; 1.4346x over previous
#include <cuda_runtime.h>

#define BB 128
#define SS 512
#define EE 512
#define HH 1024
#define VV 32000
#define NC 1000

__device__ float g_pt[(size_t)VV * 2048];     // token preactivations (+bias): [v][0..1023]=z, [1024..2047]=h
__device__ float g_wt3[128 * 1024 * 16];      // recurrent weights per block: [nb][k][g*8+c]
__device__ float g_wfc3[125 * 1024 * 8];      // classifier weights per block
__device__ float g_h[2][BB * HH];             // double-buffered hidden state
__device__ unsigned g_bar;                    // grid barrier counter

// ---- packed f32x2 helpers ----
__device__ __forceinline__ unsigned long long pack2(float a, float b) {
    unsigned long long r;
    asm("mov.b64 %0, {%1, %2};" : "=l"(r) : "f"(a), "f"(b));
    return r;
}
__device__ __forceinline__ void unpack2(unsigned long long v, float& a, float& b) {
    asm("mov.b64 {%0, %1}, %2;" : "=f"(a), "=f"(b) : "l"(v));
}
__device__ __forceinline__ void ffma2(unsigned long long& d, unsigned long long a, unsigned long long b) {
    asm("fma.rn.f32x2 %0, %1, %2, %0;" : "+l"(d) : "l"(a), "l"(b));
}
__device__ __forceinline__ void add2(unsigned long long& d, unsigned long long a) {
    asm("add.rn.f32x2 %0, %0, %1;" : "+l"(d) : "l"(a));
}
__device__ __forceinline__ float getq(float4 v, int q) {
    return q == 0 ? v.x : q == 1 ? v.y : q == 2 ? v.z : v.w;
}
__device__ __forceinline__ float4 ldcg4(const float4* p) {
    float4 v;
    asm volatile("ld.global.cg.v4.f32 {%0,%1,%2,%3},[%4];"
                 : "=f"(v.x), "=f"(v.y), "=f"(v.z), "=f"(v.w) : "l"(p));
    return v;
}

// ---------------------------------------------------------------------------
// Prep kernels
// ---------------------------------------------------------------------------
__global__ void prep_wt(const float* __restrict__ Wz, const float* __restrict__ Wh) {
    int o = blockIdx.x * blockDim.x + threadIdx.x;
    if (o >= 128 * 1024 * 16) return;
    int c = o & 7, g = (o >> 3) & 1, k = (o >> 4) & 1023, nb = o >> 14;
    const float* W = g ? Wh : Wz;
    g_wt3[o] = W[(size_t)(512 + k) * 1024 + nb * 8 + c];
}

__global__ void prep_wfc(const float* __restrict__ Wfc) {
    int o = blockIdx.x * blockDim.x + threadIdx.x;
    if (o >= 125 * 1024 * 8) return;
    int c = o & 7, k = (o >> 3) & 1023, nb = o >> 13;
    g_wfc3[o] = Wfc[(size_t)k * NC + nb * 8 + c];
}

__global__ void zero_h0() {
    int i = blockIdx.x * blockDim.x + threadIdx.x;
    if (i < BB * HH) g_h[0][i] = 0.0f;
    if (i == 0) g_bar = 0u;
}

// ---------------------------------------------------------------------------
// ptable GEMM: P[32000 x 2048] = emb @ [Wz_top | Wh_top] + bias
// ---------------------------------------------------------------------------
__global__ __launch_bounds__(256) void ptable_gemm(
    const float* __restrict__ emb,
    const float* __restrict__ Wz, const float* __restrict__ Wh,
    const float* __restrict__ bz, const float* __restrict__ bh)
{
    __shared__ float As[8][132];
    __shared__ float Bs[8][128];
    const int tid = threadIdx.x;
    const int tx = tid & 15, ty = tid >> 4;
    const int row0 = blockIdx.y * 128;
    const int col0 = blockIdx.x * 128;
    const float* W = (col0 < 1024) ? Wz : Wh;
    const int ccol0 = col0 & 1023;

    unsigned long long acc[8][4];
#pragma unroll
    for (int i = 0; i < 8; i++)
#pragma unroll
        for (int j = 0; j < 4; j++) acc[i][j] = 0ull;

    const int arow = tid >> 1;
    const int akq = (tid & 1) * 4;
    const int bkk = tid >> 5;
    const int bj = (tid & 31) * 4;

    for (int k0 = 0; k0 < EE; k0 += 8) {
        float4 av = *(const float4*)(emb + (size_t)(row0 + arow) * EE + k0 + akq);
        float4 bv = *(const float4*)(W + (size_t)(k0 + bkk) * HH + ccol0 + bj);
        As[akq + 0][arow] = av.x;
        As[akq + 1][arow] = av.y;
        As[akq + 2][arow] = av.z;
        As[akq + 3][arow] = av.w;
        *(float4*)&Bs[bkk][bj] = bv;
        __syncthreads();
#pragma unroll
        for (int kk = 0; kk < 8; kk++) {
            float4 a0 = *(const float4*)&As[kk][ty * 8];
            float4 a1 = *(const float4*)&As[kk][ty * 8 + 4];
            ulonglong2 b0 = *(const ulonglong2*)&Bs[kk][tx * 8];
            ulonglong2 b1 = *(const ulonglong2*)&Bs[kk][tx * 8 + 4];
            float a[8] = {a0.x, a0.y, a0.z, a0.w, a1.x, a1.y, a1.z, a1.w};
#pragma unroll
            for (int i = 0; i < 8; i++) {
                unsigned long long hh = pack2(a[i], a[i]);
                ffma2(acc[i][0], hh, b0.x);
                ffma2(acc[i][1], hh, b0.y);
                ffma2(acc[i][2], hh, b1.x);
                ffma2(acc[i][3], hh, b1.y);
            }
        }
        __syncthreads();
    }

    const float* bias = (col0 < 1024) ? bz : bh;
    const int colg = ccol0 + tx * 8;
    float bvv[8];
#pragma unroll
    for (int j = 0; j < 8; j++) bvv[j] = bias[colg + j];
#pragma unroll
    for (int i = 0; i < 8; i++) {
        float v[8];
        unpack2(acc[i][0], v[0], v[1]);
        unpack2(acc[i][1], v[2], v[3]);
        unpack2(acc[i][2], v[4], v[5]);
        unpack2(acc[i][3], v[6], v[7]);
#pragma unroll
        for (int j = 0; j < 8; j++) v[j] += bvv[j];
        int row = row0 + ty * 8 + i;
        float* dst = g_pt + (size_t)row * 2048 + col0 + tx * 8;
        *(float4*)dst = make_float4(v[0], v[1], v[2], v[3]);
        *(float4*)(dst + 4) = make_float4(v[4], v[5], v[6], v[7]);
    }
}

// ---------------------------------------------------------------------------
// Persistent recurrence: 128 CTAs x 512 threads, all 512 steps in one launch.
// CTA nb owns h-columns c0..c0+7 (16 gate columns: z and h-candidate).
// Thread (lane = tid&31, warp = tid>>5): rows lane+32i (i=0..3), all 16 cols,
// K-slice [warp*64, warp*64+64). Cross-warp reduce via SMEM log-tree.
// ---------------------------------------------------------------------------
__device__ __forceinline__ void quadc(unsigned long long (&acc)[4][8],
                                      const float4 (&v)[4], const float* wk) {
#pragma unroll
    for (int q = 0; q < 4; q++) {
        unsigned long long hh[4];
#pragma unroll
        for (int i = 0; i < 4; i++) { float f = getq(v[i], q); hh[i] = pack2(f, f); }
        const ulonglong2* wq = (const ulonglong2*)(wk + q * 16);
#pragma unroll
        for (int wp = 0; wp < 4; wp++) {
            ulonglong2 wv = wq[wp];
#pragma unroll
            for (int i = 0; i < 4; i++) {
                ffma2(acc[i][2 * wp], hh[i], wv.x);
                ffma2(acc[i][2 * wp + 1], hh[i], wv.y);
            }
        }
    }
}

#define RECUR_SMEM_FLOATS (16384 + 17408 + 2176)
__global__ __launch_bounds__(512, 1) void recur_kernel(const int* __restrict__ x) {
    extern __shared__ float sm[];
    float* ws = sm;                      // 16384: weights [k][16]
    float* red = sm + 16384;             // 17408: reduction tree (256 slots x 68)
    float* sums = sm + 16384 + 17408;    // 2176: final sums [r][17]

    const int tid = threadIdx.x;
    const int nb = blockIdx.x;
    const int c0 = nb * 8;

    // load this block's weights once
    {
        const float4* src = (const float4*)(g_wt3 + (size_t)nb * 16384);
        float4* dst = (float4*)ws;
#pragma unroll
        for (int i = 0; i < 8; i++) dst[tid + i * 512] = src[tid + i * 512];
    }
    __syncthreads();

    const int lane = tid & 31;
    const int warp = tid >> 5;
    const int kq0 = warp * 16;           // float4 index base in a 1024-col row
    const float* wsk = ws + (warp * 64) * 16;

    const int gr = tid >> 2;             // gate-phase row 0..127
    const int gc = (tid & 3) * 2;        // gate-phase col 0,2,4,6

    for (int t = 0; t < SS; t++) {
        const float* __restrict__ hin = g_h[t & 1];
        float* __restrict__ hout = g_h[(t & 1) ^ 1];

        // --- prefetch gate-phase inputs (consumed ~16K cycles later) ---
        int tok = x[gr * SS + t];
        const float* ptp = g_pt + (size_t)tok * 2048 + c0 + gc;
        float2 ptz = *(const float2*)ptp;
        float2 pth = *(const float2*)(ptp + 1024);
        float2 hold;
        asm volatile("ld.global.cg.v2.f32 {%0,%1},[%2];"
                     : "=f"(hold.x), "=f"(hold.y) : "l"(hin + gr * HH + c0 + gc));

        // --- main GEMV slice ---
        unsigned long long acc[4][8];
#pragma unroll
        for (int i = 0; i < 4; i++)
#pragma unroll
            for (int p = 0; p < 8; p++) acc[i][p] = 0ull;

        const float4* hb = (const float4*)hin;
        float4 A[4], B[4];
#pragma unroll
        for (int i = 0; i < 4; i++) A[i] = ldcg4(hb + (lane + 32 * i) * 256 + kq0);

#pragma unroll
        for (int j = 0; j < 16; j += 2) {
            if (j + 1 < 16) {
#pragma unroll
                for (int i = 0; i < 4; i++)
                    B[i] = ldcg4(hb + (lane + 32 * i) * 256 + kq0 + j + 1);
            }
            quadc(acc, A, wsk + (4 * j) * 16);
            if (j + 2 < 16) {
#pragma unroll
                for (int i = 0; i < 4; i++)
                    A[i] = ldcg4(hb + (lane + 32 * i) * 256 + kq0 + j + 2);
            }
            quadc(acc, B, wsk + (4 * j + 4) * 16);
        }

        // --- cross-warp reduction: 16 -> 8 -> 4 -> 2 -> 1 ---
#pragma unroll
        for (int half = 8; half >= 1; half >>= 1) {
            __syncthreads();
            if (warp >= half && warp < 2 * half) {
                float* dst = red + (((warp - half) << 5) + lane) * 68;
#pragma unroll
                for (int i = 0; i < 4; i++)
#pragma unroll
                    for (int p = 0; p < 4; p++)
                        *(ulonglong2*)(dst + i * 16 + p * 4) =
                            make_ulonglong2(acc[i][2 * p], acc[i][2 * p + 1]);
            }
            __syncthreads();
            if (warp < half) {
                const float* src = red + ((warp << 5) + lane) * 68;
#pragma unroll
                for (int i = 0; i < 4; i++)
#pragma unroll
                    for (int p = 0; p < 4; p++) {
                        ulonglong2 v = *(const ulonglong2*)(src + i * 16 + p * 4);
                        add2(acc[i][2 * p], v.x);
                        add2(acc[i][2 * p + 1], v.y);
                    }
            }
        }

        if (warp == 0) {
#pragma unroll
            for (int i = 0; i < 4; i++) {
                int r = lane + 32 * i;
#pragma unroll
                for (int p = 0; p < 8; p++) {
                    float a, b;
                    unpack2(acc[i][p], a, b);
                    sums[r * 17 + 2 * p] = a;
                    sums[r * 17 + 2 * p + 1] = b;
                }
            }
        }
        __syncthreads();

        // --- gates + state update (each thread: 2 columns of one row) ---
        {
            float zs0 = sums[gr * 17 + gc] + ptz.x;
            float zs1 = sums[gr * 17 + gc + 1] + ptz.y;
            float hs0 = sums[gr * 17 + 8 + gc] + pth.x;
            float hs1 = sums[gr * 17 + 8 + gc + 1] + pth.y;
            float z0 = 1.0f / (1.0f + __expf(-zs0));
            float z1 = 1.0f / (1.0f + __expf(-zs1));
            float th0 = tanhf(hs0);
            float th1 = tanhf(hs1);
            float hn0 = (1.0f - z0) * hold.x + z0 * th0;
            float hn1 = (1.0f - z1) * hold.y + z1 * th1;
            asm volatile("st.global.cg.v2.f32 [%0],{%1,%2};"
                         :: "l"(hout + gr * HH + c0 + gc), "f"(hn0), "f"(hn1) : "memory");
        }

        // --- grid barrier ---
        __threadfence();
        __syncthreads();
        if (tid == 0) {
            atomicAdd(&g_bar, 1u);
            unsigned target = (unsigned)(t + 1) * 128u;
            const volatile unsigned* vb = (const volatile unsigned*)&g_bar;
            while (*vb < target) {}
        }
        __syncthreads();
    }
}

// ---------------------------------------------------------------------------
// Final classifier: out[128 x 1000] = h_final @ Wfc + bfc
// ---------------------------------------------------------------------------
#define FINAL_SMEM_FLOATS (8192 + 2 * 4224 + 1152)
__global__ __launch_bounds__(256) void final_kernel(const float* __restrict__ bfc,
                                                    float* __restrict__ out) {
    extern __shared__ float sm[];
    float* ws = sm;
    float* hsm = sm + 8192;
    float* red = sm + 8192 + 2 * 4224;
    const int tid = threadIdx.x;
    const int nb = blockIdx.x;
    const int c0 = nb * 8;
    const float* hin = g_h[0];
    {
        const float4* src = (const float4*)(g_wfc3 + nb * 8192);
        float4* dst = (float4*)ws;
#pragma unroll
        for (int i = 0; i < 8; i++) dst[tid + i * 256] = src[tid + i * 256];
    }
    const int r = tid & 127, kh = tid >> 7;
    unsigned long long a0 = 0, a1 = 0, a2 = 0, a3 = 0;

    for (int j = 0; j < 16; j++) {
        __syncthreads();
#pragma unroll
        for (int i = 0; i < 8; i++) {
            int idx = tid + i * 256;
            int region = idx >> 10;
            int rem = idx & 1023;
            int rr = rem >> 3;
            int kq = (rem & 7) << 2;
            float4 hv = *(const float4*)(hin + rr * HH + region * 512 + j * 32 + kq);
            float* d = hsm + region * 4224 + rr * 33 + kq;
            d[0] = hv.x; d[1] = hv.y; d[2] = hv.z; d[3] = hv.w;
        }
        __syncthreads();
        const float* hrow = hsm + kh * 4224 + r * 33;
        const ulonglong2* wp = (const ulonglong2*)(ws + (kh * 512 + j * 32) * 8);
#pragma unroll
        for (int k = 0; k < 32; k++) {
            float hv = hrow[k];
            unsigned long long hh = pack2(hv, hv);
            ulonglong2 w0 = wp[k * 2];
            ulonglong2 w1 = wp[k * 2 + 1];
            ffma2(a0, hh, w0.x);
            ffma2(a1, hh, w0.y);
            ffma2(a2, hh, w1.x);
            ffma2(a3, hh, w1.y);
        }
    }
    float v[8];
    unpack2(a0, v[0], v[1]); unpack2(a1, v[2], v[3]);
    unpack2(a2, v[4], v[5]); unpack2(a3, v[6], v[7]);
    if (kh == 1) {
#pragma unroll
        for (int c = 0; c < 8; c++) red[r * 9 + c] = v[c];
    }
    __syncthreads();
    if (kh == 0) {
#pragma unroll
        for (int c = 0; c < 8; c++)
            out[r * NC + c0 + c] = v[c] + red[r * 9 + c] + bfc[c0 + c];
    }
}

// ---------------------------------------------------------------------------
extern "C" void kernel_launch(void* const* d_in, const int* in_sizes, int n_in,
                              void* d_out, int out_size) {
    const int*   x   = (const int*)  d_in[0];
    const float* emb = (const float*)d_in[1];
    const float* Wz  = (const float*)d_in[2];
    const float* bz  = (const float*)d_in[3];
    const float* Wh  = (const float*)d_in[4];
    const float* bh  = (const float*)d_in[5];
    const float* Wfc = (const float*)d_in[6];
    const float* bfc = (const float*)d_in[7];
    float* out = (float*)d_out;
    (void)in_sizes; (void)n_in; (void)out_size;

    const int recur_smem = RECUR_SMEM_FLOATS * 4;
    const int final_smem = FINAL_SMEM_FLOATS * 4;
    cudaFuncSetAttribute(recur_kernel, cudaFuncAttributeMaxDynamicSharedMemorySize, recur_smem);
    cudaFuncSetAttribute(final_kernel, cudaFuncAttributeMaxDynamicSharedMemorySize, final_smem);

    prep_wt<<<(128 * 1024 * 16) / 256, 256>>>(Wz, Wh);
    prep_wfc<<<(125 * 1024 * 8 + 255) / 256, 256>>>(Wfc);
    zero_h0<<<(BB * HH) / 256, 256>>>();
    ptable_gemm<<<dim3(16, 250), 256>>>(emb, Wz, Wh, bz, bh);

    recur_kernel<<<128, 512, recur_smem>>>(x);

    final_kernel<<<125, 256, final_smem>>>(bfc, out);
}